// round 5
// baseline (speedup 1.0000x reference)
#include <cuda_runtime.h>
#include <cuda_bf16.h>

// LinearPatchMerger: fused 2x2 patch-merge gather + SGEMM.
// Geometry is fixed by the problem: B=8 images, 128x128 patches, D=1024,
// merge=2 -> M=32768 merged tokens, K=4096, N=1024.
//
// merged[n, 4d+2ki+kj] = X[b*16384 + (2i+ki)*128 + (2j+kj), d]
//   with b=n>>12, i=(n&4095)>>6, j=n&63
// out[n, dout] = sum_k merged[n,k] * W[dout,k]

#define MDIM 32768
#define NDIM 1024
#define KDIM 4096

#define BM 128
#define BN 128
#define BK 16
#define TM 8
#define TN 8
#define NTHREADS 256

__global__ __launch_bounds__(NTHREADS, 2)
void merger_sgemm(const float* __restrict__ X,
                  const float* __restrict__ W,
                  float* __restrict__ O)
{
    __shared__ float As[BK][BM];        // [k][m]
    __shared__ float Bs[BK][BN + 4];    // [k][dout], +4 pad (keeps float4 alignment)

    const int tid = threadIdx.x;
    const int bn  = blockIdx.x;   // 8 N-tiles (fastest -> wave shares A slice in L2)
    const int bm  = blockIdx.y;   // 256 M-tiles

    const int tx = tid & 15;      // 16 cols of threads
    const int ty = tid >> 4;      // 16 rows of threads

    const int m_base = bm * BM;
    const int n_base = bn * BN;

    // Precompute gather source rows for this thread's two A-tile loads.
    // idx = tid + it*256 over [0,512): c = idx&3 (c = 2*ki+kj), m = idx>>2.
    int a_m[2], a_c[2];
    long a_row[2];
#pragma unroll
    for (int it = 0; it < 2; ++it) {
        int idx = tid + it * NTHREADS;
        int c = idx & 3;
        int m = idx >> 2;
        int n = m_base + m;
        int b = n >> 12;
        int t = n & 4095;
        int i = t >> 6;
        int j = t & 63;
        int ki = c >> 1;
        int kj = c & 1;
        int srow = (b << 14) + ((2 * i + ki) << 7) + (2 * j + kj);
        a_row[it] = (long)srow * 1024;
        a_m[it] = m;
        a_c[it] = c;
    }

    float acc[TM][TN];
#pragma unroll
    for (int r = 0; r < TM; ++r)
#pragma unroll
        for (int c = 0; c < TN; ++c) acc[r][c] = 0.0f;

    for (int kk = 0; kk < KDIM; kk += BK) {
        const int d0 = kk >> 2;   // feature-d base for this K chunk

        // ---- A tile: one float4 covers k-local = c, c+4, c+8, c+12 at column m
#pragma unroll
        for (int it = 0; it < 2; ++it) {
            float4 v = *reinterpret_cast<const float4*>(X + a_row[it] + d0);
            int c = a_c[it], m = a_m[it];
            As[c + 0][m]  = v.x;
            As[c + 4][m]  = v.y;
            As[c + 8][m]  = v.z;
            As[c + 12][m] = v.w;
        }

        // ---- B tile: W[dout, kk..kk+15]; 4 consecutive threads cover one dout row (64B)
#pragma unroll
        for (int it = 0; it < 2; ++it) {
            int idx = tid + it * NTHREADS;
            int kq = idx & 3;
            int dl = idx >> 2;
            float4 v = *reinterpret_cast<const float4*>(
                W + (long)(n_base + dl) * KDIM + kk + kq * 4);
            Bs[kq * 4 + 0][dl] = v.x;
            Bs[kq * 4 + 1][dl] = v.y;
            Bs[kq * 4 + 2][dl] = v.z;
            Bs[kq * 4 + 3][dl] = v.w;
        }

        __syncthreads();

#pragma unroll
        for (int kl = 0; kl < BK; ++kl) {
            float a[TM], b[TN];
            *reinterpret_cast<float4*>(&a[0]) =
                *reinterpret_cast<const float4*>(&As[kl][ty * TM]);
            *reinterpret_cast<float4*>(&a[4]) =
                *reinterpret_cast<const float4*>(&As[kl][ty * TM + 4]);
            *reinterpret_cast<float4*>(&b[0]) =
                *reinterpret_cast<const float4*>(&Bs[kl][tx * TN]);
            *reinterpret_cast<float4*>(&b[4]) =
                *reinterpret_cast<const float4*>(&Bs[kl][tx * TN + 4]);
#pragma unroll
            for (int r = 0; r < TM; ++r)
#pragma unroll
                for (int c = 0; c < TN; ++c)
                    acc[r][c] += a[r] * b[c];
        }

        __syncthreads();
    }

    // ---- epilogue: float4 stores
#pragma unroll
    for (int r = 0; r < TM; ++r) {
        int row = m_base + ty * TM + r;
        float* op = O + (long)row * NDIM + n_base + tx * TN;
        float4 v0 = make_float4(acc[r][0], acc[r][1], acc[r][2], acc[r][3]);
        float4 v1 = make_float4(acc[r][4], acc[r][5], acc[r][6], acc[r][7]);
        *reinterpret_cast<float4*>(op)     = v0;
        *reinterpret_cast<float4*>(op + 4) = v1;
    }
}

extern "C" void kernel_launch(void* const* d_in, const int* in_sizes, int n_in,
                              void* d_out, int out_size)
{
    const float* X = (const float*)d_in[0];   // image_features (1, 131072, 1024) fp32
    // d_in[1]: image_sizes (8,2) int32 — geometry is fixed (all 1792px), hardcoded
    const float* W = (const float*)d_in[2];   // (1024, 4096) fp32
    float* O = (float*)d_out;                 // (1, 32768, 1024) fp32

    dim3 grid(NDIM / BN, MDIM / BM);          // (8, 256)
    merger_sgemm<<<grid, NTHREADS>>>(X, W, O);
}

// round 7
// speedup vs baseline: 4.6691x; 4.6691x over previous
#include <cuda_runtime.h>
#include <cuda_bf16.h>
#include <cstdint>

// LinearPatchMerger via bf16 3-term-split GEMM on mma.sync (sm_103-portable
// tensor path; tcgen05 is unavailable because the harness ptxas pass targets
// plain sm_103, where all tcgen05/.cta_group features are rejected).
//
// M=32768 merged tokens, N=1024, K=4096, fp32 in/out.
// K-permutation: k' = c*1024 + d (c = 2*ki+kj); sum over k is order-invariant.
// Prepass 1: A'[n,k'] = X[srow(n,c), d] split into bf16 hi/lo (merged layout).
// Prepass 2: W'[dout,k'] = W[dout, 4d+c] split into bf16 hi/lo.
// GEMM: D = Ahi*Bhi + Ahi*Blo + Alo*Bhi, fp32 accum (lo*lo term ~2^-16, dropped).

#define MDIM 32768
#define NDIM 1024
#define KDIM 4096
#define BM 128
#define BN 128
#define BK 64
#define NCHUNKS (KDIM / BK)     // 64
#define NTHREADS 256

#define STAGE_BYTES 65536
#define OFF_AHI 0
#define OFF_ALO 16384
#define OFF_BHI 32768
#define OFF_BLO 49152
#define SMEM_TOTAL (2 * STAGE_BYTES)   // 128 KB

// One-time-per-call prepass outputs (device-global scratch; no allocations).
__device__ __nv_bfloat16 g_Ahi[(size_t)MDIM * KDIM];
__device__ __nv_bfloat16 g_Alo[(size_t)MDIM * KDIM];
__device__ __nv_bfloat16 g_Whi[(size_t)NDIM * KDIM];
__device__ __nv_bfloat16 g_Wlo[(size_t)NDIM * KDIM];

// ---------------- helpers ----------------
__device__ __forceinline__ void cpasync16(uint32_t dst, const void* src) {
    asm volatile("cp.async.cg.shared.global [%0], [%1], 16;"
                 :: "r"(dst), "l"(src));
}
__device__ __forceinline__ void cp_commit() {
    asm volatile("cp.async.commit_group;" ::: "memory");
}
template <int N>
__device__ __forceinline__ void cp_wait() {
    asm volatile("cp.async.wait_group %0;" :: "n"(N) : "memory");
}
__device__ __forceinline__ void ldsm4(uint32_t& r0, uint32_t& r1,
                                      uint32_t& r2, uint32_t& r3, uint32_t a) {
    asm volatile("ldmatrix.sync.aligned.m8n8.x4.shared.b16 {%0,%1,%2,%3}, [%4];"
                 : "=r"(r0), "=r"(r1), "=r"(r2), "=r"(r3) : "r"(a));
}
__device__ __forceinline__ void mma16816(float* c, const uint32_t* a,
                                         uint32_t b0, uint32_t b1) {
    asm volatile(
        "mma.sync.aligned.m16n8k16.row.col.f32.bf16.bf16.f32 "
        "{%0,%1,%2,%3}, {%4,%5,%6,%7}, {%8,%9}, {%0,%1,%2,%3};"
        : "+f"(c[0]), "+f"(c[1]), "+f"(c[2]), "+f"(c[3])
        : "r"(a[0]), "r"(a[1]), "r"(a[2]), "r"(a[3]), "r"(b0), "r"(b1));
}
__device__ __forceinline__ uint32_t packbf(float a, float b) {
    __nv_bfloat162 t = __floats2bfloat162_rn(a, b);
    return *reinterpret_cast<uint32_t*>(&t);
}

// ---------------- prepass: X -> merged-layout bf16 hi/lo ----------------
// One block per (merged token n, segment c): copies one contiguous 1024-float
// row of X into A'[n, c*1024 .. c*1024+1023], split into hi/lo bf16.
__global__ __launch_bounds__(256)
void x_prepass(const float* __restrict__ X) {
    const int bid = blockIdx.x;          // [0, 32768*4)
    const int n = bid >> 2;
    const int c = bid & 3;
    const int b = n >> 12;
    const int t = n & 4095;
    const int i = t >> 6;
    const int j = t & 63;
    const int ki = c >> 1, kj = c & 1;
    const long srow = ((long)b << 14) + (((i << 1) + ki) << 7) + ((j << 1) + kj);

    const int d = threadIdx.x << 2;      // 4 floats per thread
    float4 v = *reinterpret_cast<const float4*>(X + (srow << 10) + d);

    float hx = __bfloat162float(__float2bfloat16_rn(v.x));
    float hy = __bfloat162float(__float2bfloat16_rn(v.y));
    float hz = __bfloat162float(__float2bfloat16_rn(v.z));
    float hw = __bfloat162float(__float2bfloat16_rn(v.w));

    const size_t o = (size_t)n * KDIM + c * 1024 + d;
    *reinterpret_cast<uint2*>(g_Ahi + o) =
        make_uint2(packbf(hx, hy), packbf(hz, hw));
    *reinterpret_cast<uint2*>(g_Alo + o) =
        make_uint2(packbf(v.x - hx, v.y - hy), packbf(v.z - hz, v.w - hw));
}

// ---------------- prepass: W[n,4d+c] -> W'[n,c*1024+d], bf16 hi/lo ----------------
__global__ __launch_bounds__(256)
void w_prepass(const float* __restrict__ W) {
    int idx = blockIdx.x * blockDim.x + threadIdx.x;   // [0, 1024*1024)
    int n = idx >> 10;
    int d = idx & 1023;
    float4 v = *reinterpret_cast<const float4*>(W + (long)n * KDIM + 4 * d);
    float f[4] = {v.x, v.y, v.z, v.w};
#pragma unroll
    for (int c = 0; c < 4; ++c) {
        __nv_bfloat16 h = __float2bfloat16_rn(f[c]);
        float r = f[c] - __bfloat162float(h);
        size_t o = (size_t)n * KDIM + c * 1024 + d;
        g_Whi[o] = h;
        g_Wlo[o] = __float2bfloat16_rn(r);
    }
}

// ---------------- main GEMM ----------------
__global__ __launch_bounds__(NTHREADS, 1)
void merger_mma(float* __restrict__ O) {
    extern __shared__ char smem[];
    const uint32_t sb = (uint32_t)__cvta_generic_to_shared(smem);
    const int tid = threadIdx.x;
    const int m_base = blockIdx.y * BM;
    const int n_base = blockIdx.x * BN;
    const int lane = tid & 31;
    const int wid = tid >> 5;
    const int wm = (wid & 1) << 6;    // warp M offset: 0 / 64
    const int wn = (wid >> 1) << 5;   // warp N offset: 0..96
    const int lrow = lane & 15;
    const int lcol = lane >> 4;

    float acc[4][4][4];
#pragma unroll
    for (int a = 0; a < 4; ++a)
#pragma unroll
        for (int b = 0; b < 4; ++b)
#pragma unroll
            for (int q = 0; q < 4; ++q) acc[a][b][q] = 0.0f;

    auto load_stage = [&](int c) {
        const uint32_t st = sb + (uint32_t)(c & 1) * STAGE_BYTES;
        const int kb = c * BK;
#pragma unroll
        for (int i = 0; i < 4; ++i) {
            int idx = tid + i * NTHREADS;     // [0,1024)
            int row = idx >> 3;
            int s = idx & 7;
            uint32_t off = (uint32_t)((row << 7) + ((s ^ (row & 7)) << 4));
            size_t ga = (size_t)(m_base + row) * KDIM + kb + (s << 3);
            size_t gb = (size_t)(n_base + row) * KDIM + kb + (s << 3);
            cpasync16(st + OFF_AHI + off, g_Ahi + ga);
            cpasync16(st + OFF_ALO + off, g_Alo + ga);
            cpasync16(st + OFF_BHI + off, g_Whi + gb);
            cpasync16(st + OFF_BLO + off, g_Wlo + gb);
        }
    };

    auto compute = [&](int p) {
        const uint32_t st = sb + (uint32_t)p * STAGE_BYTES;
#pragma unroll
        for (int ks = 0; ks < 4; ++ks) {
            const int c16 = (ks << 1) + lcol;
            uint32_t ah[4][4], al[4][4], bh[2][4], bl[2][4];
#pragma unroll
            for (int mf = 0; mf < 4; ++mf) {
                int r = wm + (mf << 4) + lrow;
                uint32_t off = (uint32_t)((r << 7) + ((c16 ^ (r & 7)) << 4));
                ldsm4(ah[mf][0], ah[mf][1], ah[mf][2], ah[mf][3],
                      st + OFF_AHI + off);
                ldsm4(al[mf][0], al[mf][1], al[mf][2], al[mf][3],
                      st + OFF_ALO + off);
            }
#pragma unroll
            for (int nf2 = 0; nf2 < 2; ++nf2) {
                int r = wn + (nf2 << 4) + lrow;
                uint32_t off = (uint32_t)((r << 7) + ((c16 ^ (r & 7)) << 4));
                ldsm4(bh[nf2][0], bh[nf2][1], bh[nf2][2], bh[nf2][3],
                      st + OFF_BHI + off);
                ldsm4(bl[nf2][0], bl[nf2][1], bl[nf2][2], bl[nf2][3],
                      st + OFF_BLO + off);
            }
            // ldmatrix x4 (non-trans) on [rows][k] tiles:
            //   A frag regs = {m0-7/k0-7, m8-15/k0-7, m0-7/k8-15, m8-15/k8-15}
            //   B frag for n0-7 = {r0, r2}; n8-15 = {r1, r3}
#pragma unroll
            for (int mf = 0; mf < 4; ++mf) {
#pragma unroll
                for (int nf2 = 0; nf2 < 2; ++nf2) {
                    float* c0 = acc[mf][nf2 * 2 + 0];
                    float* c1 = acc[mf][nf2 * 2 + 1];
                    mma16816(c0, ah[mf], bh[nf2][0], bh[nf2][2]);
                    mma16816(c1, ah[mf], bh[nf2][1], bh[nf2][3]);
                    mma16816(c0, ah[mf], bl[nf2][0], bl[nf2][2]);
                    mma16816(c1, ah[mf], bl[nf2][1], bl[nf2][3]);
                    mma16816(c0, al[mf], bh[nf2][0], bh[nf2][2]);
                    mma16816(c1, al[mf], bh[nf2][1], bh[nf2][3]);
                }
            }
        }
    };

    load_stage(0);
    cp_commit();

    for (int c = 0; c < NCHUNKS; ++c) {
        if (c + 1 < NCHUNKS) {
            load_stage(c + 1);
            cp_commit();
            cp_wait<1>();
        } else {
            cp_wait<0>();
        }
        __syncthreads();
        compute(c & 1);
        __syncthreads();
    }

    // epilogue: float2 stores, fp32 out
    const int erow = (lane >> 2);
    const int ecol = (lane & 3) << 1;
#pragma unroll
    for (int mf = 0; mf < 4; ++mf) {
        int r0 = m_base + wm + (mf << 4) + erow;
#pragma unroll
        for (int nf = 0; nf < 4; ++nf) {
            int cc = n_base + wn + (nf << 3) + ecol;
            float* op0 = O + (size_t)r0 * NDIM + cc;
            float* op1 = O + (size_t)(r0 + 8) * NDIM + cc;
            *reinterpret_cast<float2*>(op0) =
                make_float2(acc[mf][nf][0], acc[mf][nf][1]);
            *reinterpret_cast<float2*>(op1) =
                make_float2(acc[mf][nf][2], acc[mf][nf][3]);
        }
    }
}

extern "C" void kernel_launch(void* const* d_in, const int* in_sizes, int n_in,
                              void* d_out, int out_size) {
    (void)in_sizes; (void)n_in; (void)out_size;
    const float* X = (const float*)d_in[0];   // (1, 131072, 1024) fp32
    // d_in[1]: image_sizes (8,2) int32 -- fixed geometry, hardcoded
    const float* W = (const float*)d_in[2];   // (1024, 4096) fp32
    float* O = (float*)d_out;                 // (1, 32768, 1024) fp32

    cudaFuncSetAttribute(merger_mma, cudaFuncAttributeMaxDynamicSharedMemorySize,
                         SMEM_TOTAL);

    x_prepass<<<MDIM * 4, 256>>>(X);
    w_prepass<<<(NDIM * NDIM) / 256, 256>>>(W);

    dim3 grid(NDIM / BN, MDIM / BM);          // (8, 256)
    merger_mma<<<grid, NTHREADS, SMEM_TOTAL>>>(O);
}

// round 8
// speedup vs baseline: 4.9346x; 1.0569x over previous
#include <cuda_runtime.h>
#include <cuda_bf16.h>
#include <cstdint>

// LinearPatchMerger via bf16 3-term-split GEMM on mma.sync (sm_103 portable).
// M=32768, N=1024, K=4096, fp32 in/out.
// K-permutation: k' = c*1024 + d; prepasses build merged-layout bf16 hi/lo
// copies of A and W. GEMM: D = Ahi*Bhi + Ahi*Blo + Alo*Bhi (fp32 accum).
// R8: warp tile 64x32 -> 64x64 (CTA 128x256) to cut ldmatrix bytes per MMA
// (smem-read-bound -> tensor-bound).

#define MDIM 32768
#define NDIM 1024
#define KDIM 4096
#define BM 128
#define BN 256
#define BK 64
#define NCHUNKS (KDIM / BK)     // 64
#define NTHREADS 256

#define STAGE_BYTES 98304       // A hi/lo 2*16K + B hi/lo 2*32K
#define OFF_AHI 0
#define OFF_ALO 16384
#define OFF_BHI 32768
#define OFF_BLO 65536
#define SMEM_TOTAL (2 * STAGE_BYTES)   // 192 KB

__device__ __nv_bfloat16 g_Ahi[(size_t)MDIM * KDIM];
__device__ __nv_bfloat16 g_Alo[(size_t)MDIM * KDIM];
__device__ __nv_bfloat16 g_Whi[(size_t)NDIM * KDIM];
__device__ __nv_bfloat16 g_Wlo[(size_t)NDIM * KDIM];

// ---------------- helpers ----------------
__device__ __forceinline__ void cpasync16(uint32_t dst, const void* src) {
    asm volatile("cp.async.cg.shared.global [%0], [%1], 16;"
                 :: "r"(dst), "l"(src));
}
__device__ __forceinline__ void cp_commit() {
    asm volatile("cp.async.commit_group;" ::: "memory");
}
template <int N>
__device__ __forceinline__ void cp_wait() {
    asm volatile("cp.async.wait_group %0;" :: "n"(N) : "memory");
}
__device__ __forceinline__ void ldsm4(uint32_t& r0, uint32_t& r1,
                                      uint32_t& r2, uint32_t& r3, uint32_t a) {
    asm volatile("ldmatrix.sync.aligned.m8n8.x4.shared.b16 {%0,%1,%2,%3}, [%4];"
                 : "=r"(r0), "=r"(r1), "=r"(r2), "=r"(r3) : "r"(a));
}
__device__ __forceinline__ void mma16816(float* c, const uint32_t* a,
                                         uint32_t b0, uint32_t b1) {
    asm volatile(
        "mma.sync.aligned.m16n8k16.row.col.f32.bf16.bf16.f32 "
        "{%0,%1,%2,%3}, {%4,%5,%6,%7}, {%8,%9}, {%0,%1,%2,%3};"
        : "+f"(c[0]), "+f"(c[1]), "+f"(c[2]), "+f"(c[3])
        : "r"(a[0]), "r"(a[1]), "r"(a[2]), "r"(a[3]), "r"(b0), "r"(b1));
}
__device__ __forceinline__ uint32_t packbf(float a, float b) {
    __nv_bfloat162 t = __floats2bfloat162_rn(a, b);
    return *reinterpret_cast<uint32_t*>(&t);
}

// ---------------- prepass: X -> merged-layout bf16 hi/lo ----------------
__global__ __launch_bounds__(256)
void x_prepass(const float* __restrict__ X) {
    const int bid = blockIdx.x;          // [0, 32768*4)
    const int n = bid >> 2;
    const int c = bid & 3;
    const int b = n >> 12;
    const int t = n & 4095;
    const int i = t >> 6;
    const int j = t & 63;
    const int ki = c >> 1, kj = c & 1;
    const long srow = ((long)b << 14) + (((i << 1) + ki) << 7) + ((j << 1) + kj);

    const int d = threadIdx.x << 2;
    float4 v = *reinterpret_cast<const float4*>(X + (srow << 10) + d);

    float hx = __bfloat162float(__float2bfloat16_rn(v.x));
    float hy = __bfloat162float(__float2bfloat16_rn(v.y));
    float hz = __bfloat162float(__float2bfloat16_rn(v.z));
    float hw = __bfloat162float(__float2bfloat16_rn(v.w));

    const size_t o = (size_t)n * KDIM + c * 1024 + d;
    *reinterpret_cast<uint2*>(g_Ahi + o) =
        make_uint2(packbf(hx, hy), packbf(hz, hw));
    *reinterpret_cast<uint2*>(g_Alo + o) =
        make_uint2(packbf(v.x - hx, v.y - hy), packbf(v.z - hz, v.w - hw));
}

// ---------------- prepass: W[n,4d+c] -> W'[n,c*1024+d], bf16 hi/lo ----------------
__global__ __launch_bounds__(256)
void w_prepass(const float* __restrict__ W) {
    int idx = blockIdx.x * blockDim.x + threadIdx.x;   // [0, 1024*1024)
    int n = idx >> 10;
    int d = idx & 1023;
    float4 v = *reinterpret_cast<const float4*>(W + (long)n * KDIM + 4 * d);
    float f[4] = {v.x, v.y, v.z, v.w};
#pragma unroll
    for (int c = 0; c < 4; ++c) {
        __nv_bfloat16 h = __float2bfloat16_rn(f[c]);
        float r = f[c] - __bfloat162float(h);
        size_t o = (size_t)n * KDIM + c * 1024 + d;
        g_Whi[o] = h;
        g_Wlo[o] = __float2bfloat16_rn(r);
    }
}

// ---------------- main GEMM ----------------
__global__ __launch_bounds__(NTHREADS, 1)
void merger_mma(float* __restrict__ O) {
    extern __shared__ char smem[];
    const uint32_t sb = (uint32_t)__cvta_generic_to_shared(smem);
    const int tid = threadIdx.x;
    const int m_base = blockIdx.y * BM;
    const int n_base = blockIdx.x * BN;
    const int lane = tid & 31;
    const int wid = tid >> 5;
    const int wm = (wid & 1) << 6;    // warp M offset: 0 / 64
    const int wn = (wid >> 1) << 6;   // warp N offset: 0 / 64 / 128 / 192
    const int lrow = lane & 15;
    const int lcol = lane >> 4;

    // acc[mf][nf][4]: mf -> 16-row slab, nf -> 8-col slab (8 of them = 64 N)
    float acc[4][8][4];
#pragma unroll
    for (int a = 0; a < 4; ++a)
#pragma unroll
        for (int b = 0; b < 8; ++b)
#pragma unroll
            for (int q = 0; q < 4; ++q) acc[a][b][q] = 0.0f;

    auto load_stage = [&](int c) {
        const uint32_t st = sb + (uint32_t)(c & 1) * STAGE_BYTES;
        const int kb = c * BK;
        // A: 128 rows x 128B (hi,lo)
#pragma unroll
        for (int i = 0; i < 4; ++i) {
            int idx = tid + i * NTHREADS;     // [0,1024)
            int row = idx >> 3;
            int s = idx & 7;
            uint32_t off = (uint32_t)((row << 7) + ((s ^ (row & 7)) << 4));
            size_t ga = (size_t)(m_base + row) * KDIM + kb + (s << 3);
            cpasync16(st + OFF_AHI + off, g_Ahi + ga);
            cpasync16(st + OFF_ALO + off, g_Alo + ga);
        }
        // B: 256 rows x 128B (hi,lo)
#pragma unroll
        for (int i = 0; i < 8; ++i) {
            int idx = tid + i * NTHREADS;     // [0,2048)
            int row = idx >> 3;
            int s = idx & 7;
            uint32_t off = (uint32_t)((row << 7) + ((s ^ (row & 7)) << 4));
            size_t gb = (size_t)(n_base + row) * KDIM + kb + (s << 3);
            cpasync16(st + OFF_BHI + off, g_Whi + gb);
            cpasync16(st + OFF_BLO + off, g_Wlo + gb);
        }
    };

    auto compute = [&](int p) {
        const uint32_t st = sb + (uint32_t)p * STAGE_BYTES;
#pragma unroll
        for (int ks = 0; ks < 4; ++ks) {
            const int c16 = (ks << 1) + lcol;
            uint32_t ah[4][4], al[4][4];
#pragma unroll
            for (int mf = 0; mf < 4; ++mf) {
                int r = wm + (mf << 4) + lrow;
                uint32_t off = (uint32_t)((r << 7) + ((c16 ^ (r & 7)) << 4));
                ldsm4(ah[mf][0], ah[mf][1], ah[mf][2], ah[mf][3],
                      st + OFF_AHI + off);
                ldsm4(al[mf][0], al[mf][1], al[mf][2], al[mf][3],
                      st + OFF_ALO + off);
            }
#pragma unroll
            for (int nf2 = 0; nf2 < 4; ++nf2) {
                int r = wn + (nf2 << 4) + lrow;
                uint32_t off = (uint32_t)((r << 7) + ((c16 ^ (r & 7)) << 4));
                uint32_t bh[4], bl[4];
                ldsm4(bh[0], bh[1], bh[2], bh[3], st + OFF_BHI + off);
                ldsm4(bl[0], bl[1], bl[2], bl[3], st + OFF_BLO + off);
                // B frag for n0-7 = {r0, r2}; n8-15 = {r1, r3}
#pragma unroll
                for (int mf = 0; mf < 4; ++mf) {
                    float* c0 = acc[mf][nf2 * 2 + 0];
                    float* c1 = acc[mf][nf2 * 2 + 1];
                    mma16816(c0, ah[mf], bh[0], bh[2]);
                    mma16816(c1, ah[mf], bh[1], bh[3]);
                    mma16816(c0, ah[mf], bl[0], bl[2]);
                    mma16816(c1, ah[mf], bl[1], bl[3]);
                    mma16816(c0, al[mf], bh[0], bh[2]);
                    mma16816(c1, al[mf], bh[1], bh[3]);
                }
            }
        }
    };

    load_stage(0);
    cp_commit();

    for (int c = 0; c < NCHUNKS; ++c) {
        if (c + 1 < NCHUNKS) {
            load_stage(c + 1);
            cp_commit();
            cp_wait<1>();
        } else {
            cp_wait<0>();
        }
        __syncthreads();
        compute(c & 1);
        __syncthreads();
    }

    // epilogue: float2 stores, fp32 out
    const int erow = (lane >> 2);
    const int ecol = (lane & 3) << 1;
#pragma unroll
    for (int mf = 0; mf < 4; ++mf) {
        int r0 = m_base + wm + (mf << 4) + erow;
#pragma unroll
        for (int nf = 0; nf < 8; ++nf) {
            int cc = n_base + wn + (nf << 3) + ecol;
            float* op0 = O + (size_t)r0 * NDIM + cc;
            float* op1 = O + (size_t)(r0 + 8) * NDIM + cc;
            *reinterpret_cast<float2*>(op0) =
                make_float2(acc[mf][nf][0], acc[mf][nf][1]);
            *reinterpret_cast<float2*>(op1) =
                make_float2(acc[mf][nf][2], acc[mf][nf][3]);
        }
    }
}

extern "C" void kernel_launch(void* const* d_in, const int* in_sizes, int n_in,
                              void* d_out, int out_size) {
    (void)in_sizes; (void)n_in; (void)out_size;
    const float* X = (const float*)d_in[0];   // (1, 131072, 1024) fp32
    // d_in[1]: image_sizes (8,2) int32 -- fixed geometry, hardcoded
    const float* W = (const float*)d_in[2];   // (1024, 4096) fp32
    float* O = (float*)d_out;                 // (1, 32768, 1024) fp32

    cudaFuncSetAttribute(merger_mma, cudaFuncAttributeMaxDynamicSharedMemorySize,
                         SMEM_TOTAL);

    x_prepass<<<MDIM * 4, 256>>>(X);
    w_prepass<<<(NDIM * NDIM) / 256, 256>>>(W);

    dim3 grid(NDIM / BN, MDIM / BM);          // (4, 256)
    merger_mma<<<grid, NTHREADS, SMEM_TOTAL>>>(O);
}